// round 14
// baseline (speedup 1.0000x reference)
#include <cuda_runtime.h>
#include <cuda_fp16.h>
#include <cstdint>

#define B_    4096
#define H_    2048
#define TWOH  4096

// ---------------- device scratch ----------------
__device__ __half g_Wh[(size_t)8 * TWOH * TWOH];   // [8][4096 j][4096 n] (W1 | W2 on n)
__device__ __half g_Wmh[(size_t)TWOH * H_];        // [4096 j][2048 n]
__device__ __half g_sh[(size_t)B_ * TWOH];         // [4096 m][4096 j]  (h0 | h1 on j)
__device__ __half g_gates_h[(size_t)B_ * TWOH];    // [B][4096] g1 | g2 (fp16)
__device__ __half g_merge_h[(size_t)B_ * H_];      // fp16

// ---------------- helpers ----------------
__device__ __forceinline__ uint32_t smem_u32(const void* p) {
    uint32_t a;
    asm("{ .reg .u64 t; cvta.to.shared.u64 t, %1; cvt.u32.u64 %0, t; }" : "=r"(a) : "l"(p));
    return a;
}
__device__ __forceinline__ void cpa16(uint32_t dst, const void* src) {
    asm volatile("cp.async.cg.shared.global [%0], [%1], 16;" :: "r"(dst), "l"(src));
}
#define CP_COMMIT() asm volatile("cp.async.commit_group;")
#define CP_WAIT2()  asm volatile("cp.async.wait_group 2;")
#define CP_WAIT0()  asm volatile("cp.async.wait_group 0;")

__device__ __forceinline__ uint32_t pk2h(float hi, float lo) {
    uint32_t d; asm("cvt.rn.f16x2.f32 %0, %1, %2;" : "=r"(d) : "f"(hi), "f"(lo)); return d;
}
__device__ __forceinline__ uint32_t hmul2(uint32_t a, uint32_t b) {
    uint32_t d; asm("mul.rn.f16x2 %0, %1, %2;" : "=r"(d) : "r"(a), "r"(b)); return d;
}
__device__ __forceinline__ void ldsm4(uint32_t& r0, uint32_t& r1, uint32_t& r2, uint32_t& r3,
                                      uint32_t addr) {
    asm volatile("ldmatrix.sync.aligned.m8n8.x4.shared.b16 {%0,%1,%2,%3}, [%4];"
                 : "=r"(r0), "=r"(r1), "=r"(r2), "=r"(r3) : "r"(addr));
}
__device__ __forceinline__ void ldsm4t(uint32_t& r0, uint32_t& r1, uint32_t& r2, uint32_t& r3,
                                       uint32_t addr) {
    asm volatile("ldmatrix.sync.aligned.m8n8.x4.trans.shared.b16 {%0,%1,%2,%3}, [%4];"
                 : "=r"(r0), "=r"(r1), "=r"(r2), "=r"(r3) : "r"(addr));
}
__device__ __forceinline__ void mma16(float* c, const uint32_t* a, const uint32_t* b) {
    asm volatile(
        "mma.sync.aligned.m16n8k16.row.col.f32.f16.f16.f32 "
        "{%0,%1,%2,%3}, {%4,%5,%6,%7}, {%8,%9}, {%0,%1,%2,%3};"
        : "+f"(c[0]), "+f"(c[1]), "+f"(c[2]), "+f"(c[3])
        : "r"(a[0]), "r"(a[1]), "r"(a[2]), "r"(a[3]), "r"(b[0]), "r"(b[1]));
}

// ---------------- pack kernels (8 halfs/thread) ----------------
__global__ __launch_bounds__(256) void pack_W(const float* __restrict__ W1,
                                              const float* __restrict__ W2,
                                              __half* __restrict__ dst) {
    const size_t idx = ((size_t)blockIdx.x * 256 + threadIdx.x) * 8;
    const int ng = (int)(idx & (TWOH - 1));
    const size_t ij = idx >> 12;
    const float* src = (ng < H_) ? (W1 + ij * H_ + ng) : (W2 + ij * H_ + (ng - H_));
    const float4 v0 = *(const float4*)src;
    const float4 v1 = *(const float4*)(src + 4);
    uint4 o;
    o.x = pk2h(v0.y, v0.x); o.y = pk2h(v0.w, v0.z);
    o.z = pk2h(v1.y, v1.x); o.w = pk2h(v1.w, v1.z);
    *(uint4*)(dst + idx) = o;
}
__global__ __launch_bounds__(256) void pack_s(const float* __restrict__ h0,
                                              const float* __restrict__ h1,
                                              __half* __restrict__ dst) {
    const size_t idx = ((size_t)blockIdx.x * 256 + threadIdx.x) * 8;
    const int j = (int)(idx & (TWOH - 1));
    const size_t m = idx >> 12;
    const float* src = (j < H_) ? (h0 + m * H_ + j) : (h1 + m * H_ + (j - H_));
    const float4 v0 = *(const float4*)src;
    const float4 v1 = *(const float4*)(src + 4);
    uint4 o;
    o.x = pk2h(v0.y, v0.x); o.y = pk2h(v0.w, v0.z);
    o.z = pk2h(v1.y, v1.x); o.w = pk2h(v1.w, v1.z);
    *(uint4*)(dst + idx) = o;
}
__global__ __launch_bounds__(256) void pack_Wm(const float* __restrict__ src,
                                               __half* __restrict__ dst) {
    const size_t idx = ((size_t)blockIdx.x * 256 + threadIdx.x) * 8;
    const float4 v0 = *(const float4*)(src + idx);
    const float4 v1 = *(const float4*)(src + idx + 4);
    uint4 o;
    o.x = pk2h(v0.y, v0.x); o.y = pk2h(v0.w, v0.z);
    o.z = pk2h(v1.y, v1.x); o.w = pk2h(v1.w, v1.z);
    *(uint4*)(dst + idx) = o;
}

// ---------------- smem layout (bytes) ----------------
#define GA_ROW    40                       // A row stride (halfs)
#define GA_STG_B  (128 * GA_ROW * 2)       // 10240
#define GB_ROWB   144                      // B row stride (bytes) = 64n halfs + 8 pad
#define GB_STG_B  (64 * GB_ROWB)           // 9216
#define GB_OFF_B  (2 * GA_STG_B)           // 20480
#define GXD_OFF_W ((GB_OFF_B + 4 * GB_STG_B) / 4)   // word idx 14336
#define G_SMEM_B  (GB_OFF_B + 4 * GB_STG_B + 128 * 9 * 4)   // 61952
// merge: A 4 stg; B 4 stg x [32 k x 144 B]
#define MB_STG_B  (32 * GB_ROWB)           // 4608
#define MB_OFF_B  (4 * GA_STG_B)           // 40960

// ===========================================================================
// Fused GEMM. Tiles 0..2047: gates (CTA 128m x 64n); 2048..3071: merge.
// Gates: 512 steps, K=64/step, 4-stage B ring, wait_group 2. 3 CTAs/SM.
// ===========================================================================
__global__ __launch_bounds__(256, 3) void fused_mma(
    const __half* __restrict__ Wh, const __half* __restrict__ Wmh,
    const __half* __restrict__ sh,
    const float* __restrict__ x0, const float* __restrict__ x1)
{
    extern __shared__ __align__(16) char smc[];
    uint32_t* usm = (uint32_t*)smc;
    const uint32_t smb = smem_u32(smc);
    const int tid = threadIdx.x, lane = tid & 31, wid = tid >> 5;
    const int wm = wid & 3, wn = wid >> 2;
    const int lr = lane >> 2, lc = lane & 3;
    const int tile = blockIdx.x;

    const uint32_t a_lane_off = (uint32_t)(lane & 15) * (GA_ROW * 2) +
                                ((lane >> 4) & 1) * 16;
    const uint32_t b_lane_off = (uint32_t)(lane & 15) * GB_ROWB +
                                (uint32_t)(wn * 32 + ((lane >> 4) << 3)) * 2;

    float acc[2][4][4];
#pragma unroll
    for (int mt = 0; mt < 2; mt++)
#pragma unroll
        for (int nt = 0; nt < 4; nt++)
#pragma unroll
            for (int q = 0; q < 4; q++) acc[mt][nt][q] = 0.f;

    if (tile < 2048) {
        // ================= gates path =================
        const int m0 = (tile & 31) * 128;       // m fastest -> W dedup in L2
        const int n0 = (tile >> 5) * 64;

        // xd: duplicated half2 x-scales [128 rows][8 i], stride 9 words
        for (int idx = tid; idx < 1024; idx += 256) {
            const int row = idx >> 3, i = idx & 7;
            const float v = (i < 4) ? x0[(size_t)(m0 + row) * 4 + i]
                                    : x1[(size_t)(m0 + row) * 4 + (i - 4)];
            usm[GXD_OFF_W + row * 9 + i] = pk2h(v, v);
        }

        // B stage: 64 k-rows (2 slabs x 32 j) x 64 n; 2 cpa16/thread
        auto issue_B = [&](int s) {
            const int jb = s >> 2, i0 = (s & 3) * 2, st = s & 3;
#pragma unroll
            for (int it = 0; it < 2; it++) {
                const int idx = it * 256 + tid, row = idx >> 3, c = idx & 7;
                const int slab = i0 + (row >> 5), jr = jb * 32 + (row & 31);
                cpa16(smb + GB_OFF_B + (uint32_t)(st * GB_STG_B + row * GB_ROWB + c * 16),
                      Wh + ((size_t)slab * TWOH + jr) * TWOH + n0 + c * 8);
            }
        };
        auto issue_A = [&](int jb) {
#pragma unroll
            for (int it = 0; it < 2; it++) {
                const int idx = it * 256 + tid, row = idx >> 2, c = idx & 3;
                cpa16(smb + (uint32_t)(((jb & 1) * 128 + row) * GA_ROW + c * 8) * 2,
                      sh + (size_t)(m0 + row) * TWOH + jb * 32 + c * 8);
            }
        };

        issue_A(0); issue_B(0); CP_COMMIT();
        issue_B(1); CP_COMMIT();
        issue_B(2); CP_COMMIT();

        uint32_t areg[2][2][4];

        for (int s = 0; s < 512; s++) {
            const int jb = s >> 2, q = s & 3, i0 = q * 2;

            if (s >= 509) { CP_WAIT0(); } else { CP_WAIT2(); }
            __syncthreads();

            if (q == 0) {
                const uint32_t ab = smb + (uint32_t)((jb & 1) * 128 + wm * 32) * (GA_ROW * 2);
#pragma unroll
                for (int mt = 0; mt < 2; mt++)
#pragma unroll
                    for (int ks = 0; ks < 2; ks++)
                        ldsm4(areg[mt][ks][0], areg[mt][ks][1],
                              areg[mt][ks][2], areg[mt][ks][3],
                              ab + (uint32_t)mt * 16 * (GA_ROW * 2) + a_lane_off + ks * 32);
            }

            uint32_t xd[2][4];
#pragma unroll
            for (int h = 0; h < 2; h++)
#pragma unroll
                for (int mt = 0; mt < 2; mt++) {
                    xd[h][mt * 2]     = usm[GXD_OFF_W + (wm * 32 + mt * 16 + lr) * 9 + i0 + h];
                    xd[h][mt * 2 + 1] = usm[GXD_OFF_W + (wm * 32 + mt * 16 + 8 + lr) * 9 + i0 + h];
                }

            const uint32_t bb = smb + GB_OFF_B + (uint32_t)(s & 3) * GB_STG_B;
#pragma unroll
            for (int h = 0; h < 2; h++) {
                const uint32_t bh = bb + (uint32_t)h * 32 * GB_ROWB;
#pragma unroll
                for (int ks = 0; ks < 2; ks++) {
                    uint32_t bfr[4][2];
#pragma unroll
                    for (int p = 0; p < 2; p++) {
                        uint32_t r0, r1, r2, r3;
                        ldsm4t(r0, r1, r2, r3,
                               bh + (uint32_t)ks * 16 * GB_ROWB + b_lane_off + p * 32);
                        bfr[2 * p][0] = r0; bfr[2 * p][1] = r1;
                        bfr[2 * p + 1][0] = r2; bfr[2 * p + 1][1] = r3;
                    }
#pragma unroll
                    for (int mt = 0; mt < 2; mt++) {
                        uint32_t a[4];
                        a[0] = hmul2(areg[mt][ks][0], xd[h][2 * mt]);
                        a[1] = hmul2(areg[mt][ks][1], xd[h][2 * mt + 1]);
                        a[2] = hmul2(areg[mt][ks][2], xd[h][2 * mt]);
                        a[3] = hmul2(areg[mt][ks][3], xd[h][2 * mt + 1]);
#pragma unroll
                        for (int nt = 0; nt < 4; nt++) mma16(acc[mt][nt], a, bfr[nt]);
                    }
                }
            }

            if (s + 3 < 512) {
                issue_B(s + 3);
                if (q == 0 && jb + 1 < 128) issue_A(jb + 1);
                CP_COMMIT();
            }
        }

#pragma unroll
        for (int mt = 0; mt < 2; mt++) {
            const int rg = m0 + wm * 32 + mt * 16 + lr;
#pragma unroll
            for (int nt = 0; nt < 4; nt++) {
                const int cg = n0 + wn * 32 + nt * 8 + 2 * lc;
                *(uint32_t*)(g_gates_h + (size_t)rg * TWOH + cg) =
                    pk2h(acc[mt][nt][1], acc[mt][nt][0]);
                *(uint32_t*)(g_gates_h + (size_t)(rg + 8) * TWOH + cg) =
                    pk2h(acc[mt][nt][3], acc[mt][nt][2]);
            }
        }
    } else {
        // ================= merge path =================
        const int t = tile - 2048;
        const int m0 = (t & 31) * 128;
        const int n0 = (t >> 5) * 64;

        auto issue_AB = [&](int s) {
            const int st = s & 3;
#pragma unroll
            for (int it = 0; it < 2; it++) {
                const int idx = it * 256 + tid, row = idx >> 2, c = idx & 3;
                cpa16(smb + (uint32_t)((st * 128 + row) * GA_ROW + c * 8) * 2,
                      sh + (size_t)(m0 + row) * TWOH + s * 32 + c * 8);
            }
            {
                const int row = tid >> 3, c = tid & 7;
                cpa16(smb + MB_OFF_B + (uint32_t)(st * MB_STG_B + row * GB_ROWB + c * 16),
                      Wmh + (size_t)(s * 32 + row) * H_ + n0 + c * 8);
            }
        };

        issue_AB(0); CP_COMMIT();
        issue_AB(1); CP_COMMIT();
        issue_AB(2); CP_COMMIT();

        for (int s = 0; s < 128; s++) {
            if (s >= 125) { CP_WAIT0(); } else { CP_WAIT2(); }
            __syncthreads();

            uint32_t areg[2][2][4];
            const uint32_t ab = smb + (uint32_t)((s & 3) * 128 + wm * 32) * (GA_ROW * 2);
#pragma unroll
            for (int mt = 0; mt < 2; mt++)
#pragma unroll
                for (int ks = 0; ks < 2; ks++)
                    ldsm4(areg[mt][ks][0], areg[mt][ks][1], areg[mt][ks][2], areg[mt][ks][3],
                          ab + (uint32_t)mt * 16 * (GA_ROW * 2) + a_lane_off + ks * 32);

            const uint32_t bb = smb + MB_OFF_B + (uint32_t)(s & 3) * MB_STG_B;
#pragma unroll
            for (int ks = 0; ks < 2; ks++) {
                uint32_t bfr[4][2];
#pragma unroll
                for (int p = 0; p < 2; p++) {
                    uint32_t r0, r1, r2, r3;
                    ldsm4t(r0, r1, r2, r3,
                           bb + (uint32_t)ks * 16 * GB_ROWB + b_lane_off + p * 32);
                    bfr[2 * p][0] = r0; bfr[2 * p][1] = r1;
                    bfr[2 * p + 1][0] = r2; bfr[2 * p + 1][1] = r3;
                }
#pragma unroll
                for (int mt = 0; mt < 2; mt++)
#pragma unroll
                    for (int nt = 0; nt < 4; nt++)
                        mma16(acc[mt][nt], areg[mt][ks], bfr[nt]);
            }

            if (s + 3 < 128) { issue_AB(s + 3); CP_COMMIT(); }
        }

#pragma unroll
        for (int mt = 0; mt < 2; mt++) {
            const int rg = m0 + wm * 32 + mt * 16 + lr;
#pragma unroll
            for (int nt = 0; nt < 4; nt++) {
                const int cg = n0 + wn * 32 + nt * 8 + 2 * lc;
                *(uint32_t*)(g_merge_h + (size_t)rg * H_ + cg) =
                    pk2h(acc[mt][nt][1], acc[mt][nt][0]);
                *(uint32_t*)(g_merge_h + (size_t)(rg + 8) * H_ + cg) =
                    pk2h(acc[mt][nt][3], acc[mt][nt][2]);
            }
        }
    }
}

// ===========================================================================
// Epilogue (fp16 scratch reads)
// ===========================================================================
__global__ __launch_bounds__(256) void epilogue_kernel(
    const float* __restrict__ b1, const float* __restrict__ b2,
    float* __restrict__ out)
{
    const size_t idx = ((size_t)blockIdx.x * 256 + threadIdx.x) * 4;
    const int n = (int)(idx & (H_ - 1));
    const size_t m = idx >> 11;

    const uint2 h1 = *(const uint2*)(g_gates_h + m * TWOH + n);
    const uint2 h2 = *(const uint2*)(g_gates_h + m * TWOH + H_ + n);
    const uint2 hm = *(const uint2*)(g_merge_h + idx);
    const float4 v1 = *(const float4*)(b1 + n);
    const float4 v2 = *(const float4*)(b2 + n);

    const float2 g1a = __half22float2(*(const __half2*)&h1.x);
    const float2 g1b = __half22float2(*(const __half2*)&h1.y);
    const float2 g2a = __half22float2(*(const __half2*)&h2.x);
    const float2 g2b = __half22float2(*(const __half2*)&h2.y);
    const float2 mva = __half22float2(*(const __half2*)&hm.x);
    const float2 mvb = __half22float2(*(const __half2*)&hm.y);

    float4 r;
    { const float st = tanhf(g1a.x + v1.x);
      const float u = 1.0f / (1.0f + __expf(-(g2a.x + v2.x)));
      r.x = u * st + (1.0f - u) * mva.x; }
    { const float st = tanhf(g1a.y + v1.y);
      const float u = 1.0f / (1.0f + __expf(-(g2a.y + v2.y)));
      r.y = u * st + (1.0f - u) * mva.y; }
    { const float st = tanhf(g1b.x + v1.z);
      const float u = 1.0f / (1.0f + __expf(-(g2b.x + v2.z)));
      r.z = u * st + (1.0f - u) * mvb.x; }
    { const float st = tanhf(g1b.y + v1.w);
      const float u = 1.0f / (1.0f + __expf(-(g2b.y + v2.w)));
      r.w = u * st + (1.0f - u) * mvb.y; }

    *(float4*)(out + idx) = r;
    *(float4*)(out + idx + (size_t)B_ * H_) = r;
}

// ===========================================================================
extern "C" void kernel_launch(void* const* d_in, const int* in_sizes, int n_in,
                              void* d_out, int out_size)
{
    const float* x0 = (const float*)d_in[0];
    const float* x1 = (const float*)d_in[1];
    const float* h0 = (const float*)d_in[2];
    const float* h1 = (const float*)d_in[3];
    const float* W1 = (const float*)d_in[4];
    const float* b1 = (const float*)d_in[5];
    const float* W2 = (const float*)d_in[6];
    const float* b2 = (const float*)d_in[7];
    const float* Wm = (const float*)d_in[8];
    float* out = (float*)d_out;

    __half *wh, *wmh, *sh;
    cudaGetSymbolAddress((void**)&wh, g_Wh);
    cudaGetSymbolAddress((void**)&wmh, g_Wmh);
    cudaGetSymbolAddress((void**)&sh, g_sh);

    static bool attr_set = false;
    if (!attr_set) {
        cudaFuncSetAttribute(fused_mma, cudaFuncAttributeMaxDynamicSharedMemorySize, G_SMEM_B);
        attr_set = true;
    }

    pack_W <<<65536, 256>>>(W1, W2, wh);
    pack_s <<<8192, 256>>>(h0, h1, sh);
    pack_Wm<<<4096, 256>>>(Wm, wmh);

    fused_mma<<<3072, 256, G_SMEM_B>>>(wh, wmh, sh, x0, x1);

    epilogue_kernel<<<(unsigned)((size_t)B_ * H_ / 4 / 256), 256>>>(b1, b2, out);
}

// round 15
// speedup vs baseline: 1.0192x; 1.0192x over previous
#include <cuda_runtime.h>
#include <cuda_fp16.h>
#include <cstdint>

#define B_    4096
#define H_    2048
#define TWOH  4096

// ---------------- device scratch ----------------
__device__ __half g_Wh[(size_t)8 * TWOH * TWOH];   // [8][4096 j][4096 n] (W1 | W2 on n)
__device__ __half g_Wmh[(size_t)TWOH * H_];        // [4096 j][2048 n]
__device__ __half g_sh[(size_t)B_ * TWOH];         // [4096 m][4096 j]  (h0 | h1 on j)
__device__ __half g_gates_h[(size_t)B_ * TWOH];    // [B][4096] g1 | g2 (fp16)
__device__ __half g_merge_h[(size_t)B_ * H_];      // fp16

// ---------------- helpers ----------------
__device__ __forceinline__ uint32_t smem_u32(const void* p) {
    uint32_t a;
    asm("{ .reg .u64 t; cvta.to.shared.u64 t, %1; cvt.u32.u64 %0, t; }" : "=r"(a) : "l"(p));
    return a;
}
__device__ __forceinline__ void cpa16(uint32_t dst, const void* src) {
    asm volatile("cp.async.cg.shared.global [%0], [%1], 16;" :: "r"(dst), "l"(src));
}
#define CP_COMMIT() asm volatile("cp.async.commit_group;")
#define CP_WAIT2()  asm volatile("cp.async.wait_group 2;")
#define CP_WAIT0()  asm volatile("cp.async.wait_group 0;")

__device__ __forceinline__ uint32_t pk2h(float hi, float lo) {
    uint32_t d; asm("cvt.rn.f16x2.f32 %0, %1, %2;" : "=r"(d) : "f"(hi), "f"(lo)); return d;
}
__device__ __forceinline__ uint32_t hmul2(uint32_t a, uint32_t b) {
    uint32_t d; asm("mul.rn.f16x2 %0, %1, %2;" : "=r"(d) : "r"(a), "r"(b)); return d;
}
__device__ __forceinline__ void ldsm4(uint32_t& r0, uint32_t& r1, uint32_t& r2, uint32_t& r3,
                                      uint32_t addr) {
    asm volatile("ldmatrix.sync.aligned.m8n8.x4.shared.b16 {%0,%1,%2,%3}, [%4];"
                 : "=r"(r0), "=r"(r1), "=r"(r2), "=r"(r3) : "r"(addr));
}
__device__ __forceinline__ void ldsm4t(uint32_t& r0, uint32_t& r1, uint32_t& r2, uint32_t& r3,
                                       uint32_t addr) {
    asm volatile("ldmatrix.sync.aligned.m8n8.x4.trans.shared.b16 {%0,%1,%2,%3}, [%4];"
                 : "=r"(r0), "=r"(r1), "=r"(r2), "=r"(r3) : "r"(addr));
}
__device__ __forceinline__ void mma16(float* c, const uint32_t* a, const uint32_t* b) {
    asm volatile(
        "mma.sync.aligned.m16n8k16.row.col.f32.f16.f16.f32 "
        "{%0,%1,%2,%3}, {%4,%5,%6,%7}, {%8,%9}, {%0,%1,%2,%3};"
        : "+f"(c[0]), "+f"(c[1]), "+f"(c[2]), "+f"(c[3])
        : "r"(a[0]), "r"(a[1]), "r"(a[2]), "r"(a[3]), "r"(b[0]), "r"(b[1]));
}

// ---------------- fused pack kernel (single launch) ----------------
// blocks [0, 65536):           W1|W2 -> g_Wh
// blocks [65536, 69632):       Wm    -> g_Wmh
// blocks [69632, 77824):       h0|h1 -> g_sh
__global__ __launch_bounds__(256) void pack_all(
    const float* __restrict__ W1, const float* __restrict__ W2,
    const float* __restrict__ Wm,
    const float* __restrict__ h0, const float* __restrict__ h1,
    __half* __restrict__ wh, __half* __restrict__ wmh, __half* __restrict__ shd)
{
    const int b = blockIdx.x;
    const float* src;
    __half* dst;
    size_t idx;
    if (b < 65536) {
        idx = ((size_t)b * 256 + threadIdx.x) * 8;
        const int ng = (int)(idx & (TWOH - 1));
        const size_t ij = idx >> 12;
        src = (ng < H_) ? (W1 + ij * H_ + ng) : (W2 + ij * H_ + (ng - H_));
        dst = wh + idx;
    } else if (b < 69632) {
        idx = ((size_t)(b - 65536) * 256 + threadIdx.x) * 8;
        src = Wm + idx;
        dst = wmh + idx;
    } else {
        idx = ((size_t)(b - 69632) * 256 + threadIdx.x) * 8;
        const int j = (int)(idx & (TWOH - 1));
        const size_t m = idx >> 12;
        src = (j < H_) ? (h0 + m * H_ + j) : (h1 + m * H_ + (j - H_));
        dst = shd + idx;
    }
    const float4 v0 = *(const float4*)src;
    const float4 v1 = *(const float4*)(src + 4);
    uint4 o;
    o.x = pk2h(v0.y, v0.x); o.y = pk2h(v0.w, v0.z);
    o.z = pk2h(v1.y, v1.x); o.w = pk2h(v1.w, v1.z);
    *(uint4*)dst = o;
}

// ---------------- smem layout (R13) ----------------
#define GA_ROW    40
#define GA_STG    (128 * GA_ROW)            // 5120 halfs (10240 B)
#define GB_ROW    136
#define GB_STG    (64 * GB_ROW)             // 8704 halfs (17408 B)
#define GB_OFF_B  (2 * GA_STG * 2)          // 20480 bytes
#define GXD_OFF_W ((GB_OFF_B + 4 * GB_STG * 2) / 4)
#define G_SMEM_B  (GB_OFF_B + 4 * GB_STG * 2 + 128 * 9 * 4)   // 94720
#define MB_STG    (32 * GB_ROW)             // 4352 halfs
#define MB_OFF_B  (4 * GA_STG * 2)          // 40960 bytes

// ===========================================================================
// Fused GEMM kernel. Tiles 0..1023: gates; 1024..1535: merge.
// Gates: R13 mainloop (4-stage, K=64, wait2), prefetch issued BEFORE compute.
// fp16 writeback.
// ===========================================================================
__global__ __launch_bounds__(256, 2) void fused_mma(
    const __half* __restrict__ Wh, const __half* __restrict__ Wmh,
    const __half* __restrict__ sh,
    const float* __restrict__ x0, const float* __restrict__ x1)
{
    extern __shared__ __align__(16) char smc[];
    uint32_t* usm = (uint32_t*)smc;
    const uint32_t smb = smem_u32(smc);
    const int tid = threadIdx.x, lane = tid & 31, wid = tid >> 5;
    const int wm = wid & 3, wn = wid >> 2;
    const int lr = lane >> 2, lc = lane & 3;
    const int tile = blockIdx.x;

    const uint32_t a_lane_off = (uint32_t)(lane & 15) * (GA_ROW * 2) +
                                ((lane >> 4) & 1) * 16;
    const uint32_t b_lane_off = (uint32_t)(lane & 15) * (GB_ROW * 2) +
                                (uint32_t)(wn * 64 + ((lane >> 4) << 3)) * 2;

    float acc[2][8][4];
#pragma unroll
    for (int mt = 0; mt < 2; mt++)
#pragma unroll
        for (int nt = 0; nt < 8; nt++)
#pragma unroll
            for (int q = 0; q < 4; q++) acc[mt][nt][q] = 0.f;

    if (tile < 1024) {
        // ================= gates path =================
        const int m0 = (tile & 31) * 128;       // m fastest -> W dedup in L2
        const int n0 = (tile >> 5) * 128;

        for (int idx = tid; idx < 1024; idx += 256) {
            const int row = idx >> 3, i = idx & 7;
            const float v = (i < 4) ? x0[(size_t)(m0 + row) * 4 + i]
                                    : x1[(size_t)(m0 + row) * 4 + (i - 4)];
            usm[GXD_OFF_W + row * 9 + i] = pk2h(v, v);
        }

        auto issue_B = [&](int s) {
            const int jb = s >> 2, i0 = (s & 3) * 2, st = s & 3;
#pragma unroll
            for (int it = 0; it < 4; it++) {
                const int idx = it * 256 + tid, row = idx >> 4, c = idx & 15;
                const int slab = i0 + (row >> 5), jr = jb * 32 + (row & 31);
                cpa16(smb + GB_OFF_B + (uint32_t)(st * GB_STG + row * GB_ROW + c * 8) * 2,
                      Wh + ((size_t)slab * TWOH + jr) * TWOH + n0 + c * 8);
            }
        };
        auto issue_A = [&](int jb) {
#pragma unroll
            for (int it = 0; it < 2; it++) {
                const int idx = it * 256 + tid, row = idx >> 2, c = idx & 3;
                cpa16(smb + (uint32_t)(((jb & 1) * 128 + row) * GA_ROW + c * 8) * 2,
                      sh + (size_t)(m0 + row) * TWOH + jb * 32 + c * 8);
            }
        };

        issue_A(0); issue_B(0); CP_COMMIT();
        issue_B(1); CP_COMMIT();
        issue_B(2); CP_COMMIT();

        uint32_t areg[2][2][4];

        for (int s = 0; s < 512; s++) {
            const int jb = s >> 2, q = s & 3, i0 = q * 2;

            if (s >= 509) { CP_WAIT0(); } else { CP_WAIT2(); }
            __syncthreads();

            // ---- prefetch FIRST: maximum flight time before its wait ----
            if (s + 3 < 512) {
                issue_B(s + 3);
                if (q == 0 && jb + 1 < 128) issue_A(jb + 1);
                CP_COMMIT();
            }

            if (q == 0) {
                const uint32_t ab = smb + (uint32_t)((jb & 1) * 128 + wm * 32) * (GA_ROW * 2);
#pragma unroll
                for (int mt = 0; mt < 2; mt++)
#pragma unroll
                    for (int ks = 0; ks < 2; ks++)
                        ldsm4(areg[mt][ks][0], areg[mt][ks][1],
                              areg[mt][ks][2], areg[mt][ks][3],
                              ab + (uint32_t)mt * 16 * (GA_ROW * 2) + a_lane_off + ks * 32);
            }

            uint32_t xd[2][4];
#pragma unroll
            for (int h = 0; h < 2; h++)
#pragma unroll
                for (int mt = 0; mt < 2; mt++) {
                    xd[h][mt * 2]     = usm[GXD_OFF_W + (wm * 32 + mt * 16 + lr) * 9 + i0 + h];
                    xd[h][mt * 2 + 1] = usm[GXD_OFF_W + (wm * 32 + mt * 16 + 8 + lr) * 9 + i0 + h];
                }

            const uint32_t bb = smb + GB_OFF_B + (uint32_t)(s & 3) * (GB_STG * 2);
#pragma unroll
            for (int h = 0; h < 2; h++) {
                const uint32_t bh = bb + (uint32_t)h * 32 * (GB_ROW * 2);
#pragma unroll
                for (int ks = 0; ks < 2; ks++) {
                    uint32_t bfr[8][2];
#pragma unroll
                    for (int p = 0; p < 4; p++) {
                        uint32_t r0, r1, r2, r3;
                        ldsm4t(r0, r1, r2, r3,
                               bh + (uint32_t)ks * 16 * (GB_ROW * 2) + b_lane_off + p * 32);
                        bfr[2 * p][0] = r0; bfr[2 * p][1] = r1;
                        bfr[2 * p + 1][0] = r2; bfr[2 * p + 1][1] = r3;
                    }
#pragma unroll
                    for (int mt = 0; mt < 2; mt++) {
                        uint32_t a[4];
                        a[0] = hmul2(areg[mt][ks][0], xd[h][2 * mt]);
                        a[1] = hmul2(areg[mt][ks][1], xd[h][2 * mt + 1]);
                        a[2] = hmul2(areg[mt][ks][2], xd[h][2 * mt]);
                        a[3] = hmul2(areg[mt][ks][3], xd[h][2 * mt + 1]);
#pragma unroll
                        for (int nt = 0; nt < 8; nt++) mma16(acc[mt][nt], a, bfr[nt]);
                    }
                }
            }
        }

#pragma unroll
        for (int mt = 0; mt < 2; mt++) {
            const int rg = m0 + wm * 32 + mt * 16 + lr;
#pragma unroll
            for (int nt = 0; nt < 8; nt++) {
                const int cg = n0 + wn * 64 + nt * 8 + 2 * lc;
                *(uint32_t*)(g_gates_h + (size_t)rg * TWOH + cg) =
                    pk2h(acc[mt][nt][1], acc[mt][nt][0]);
                *(uint32_t*)(g_gates_h + (size_t)(rg + 8) * TWOH + cg) =
                    pk2h(acc[mt][nt][3], acc[mt][nt][2]);
            }
        }
    } else {
        // ================= merge path =================
        const int t = tile - 1024;
        const int m0 = (t & 31) * 128;
        const int n0 = (t >> 5) * 128;

        auto issue_AB = [&](int s) {
            const int st = s & 3;
#pragma unroll
            for (int it = 0; it < 2; it++) {
                const int idx = it * 256 + tid, row = idx >> 2, c = idx & 3;
                cpa16(smb + (uint32_t)((st * 128 + row) * GA_ROW + c * 8) * 2,
                      sh + (size_t)(m0 + row) * TWOH + s * 32 + c * 8);
            }
#pragma unroll
            for (int it = 0; it < 2; it++) {
                const int idx = it * 256 + tid, row = idx >> 4, c = idx & 15;
                cpa16(smb + MB_OFF_B + (uint32_t)(st * MB_STG + row * GB_ROW + c * 8) * 2,
                      Wmh + (size_t)(s * 32 + row) * H_ + n0 + c * 8);
            }
        };

        issue_AB(0); CP_COMMIT();
        issue_AB(1); CP_COMMIT();
        issue_AB(2); CP_COMMIT();

        for (int s = 0; s < 128; s++) {
            if (s >= 125) { CP_WAIT0(); } else { CP_WAIT2(); }
            __syncthreads();

            if (s + 3 < 128) { issue_AB(s + 3); CP_COMMIT(); }

            uint32_t areg[2][2][4];
            const uint32_t ab = smb + (uint32_t)((s & 3) * 128 + wm * 32) * (GA_ROW * 2);
#pragma unroll
            for (int mt = 0; mt < 2; mt++)
#pragma unroll
                for (int ks = 0; ks < 2; ks++)
                    ldsm4(areg[mt][ks][0], areg[mt][ks][1], areg[mt][ks][2], areg[mt][ks][3],
                          ab + (uint32_t)mt * 16 * (GA_ROW * 2) + a_lane_off + ks * 32);

            const uint32_t bb = smb + MB_OFF_B + (uint32_t)((s & 3) * MB_STG) * 2;
#pragma unroll
            for (int ks = 0; ks < 2; ks++) {
                uint32_t bfr[8][2];
#pragma unroll
                for (int p = 0; p < 4; p++) {
                    uint32_t r0, r1, r2, r3;
                    ldsm4t(r0, r1, r2, r3,
                           bb + (uint32_t)ks * 16 * (GB_ROW * 2) + b_lane_off + p * 32);
                    bfr[2 * p][0] = r0; bfr[2 * p][1] = r1;
                    bfr[2 * p + 1][0] = r2; bfr[2 * p + 1][1] = r3;
                }
#pragma unroll
                for (int mt = 0; mt < 2; mt++)
#pragma unroll
                    for (int nt = 0; nt < 8; nt++)
                        mma16(acc[mt][nt], areg[mt][ks], bfr[nt]);
            }
        }

#pragma unroll
        for (int mt = 0; mt < 2; mt++) {
            const int rg = m0 + wm * 32 + mt * 16 + lr;
#pragma unroll
            for (int nt = 0; nt < 8; nt++) {
                const int cg = n0 + wn * 64 + nt * 8 + 2 * lc;
                *(uint32_t*)(g_merge_h + (size_t)rg * H_ + cg) =
                    pk2h(acc[mt][nt][1], acc[mt][nt][0]);
                *(uint32_t*)(g_merge_h + (size_t)(rg + 8) * H_ + cg) =
                    pk2h(acc[mt][nt][3], acc[mt][nt][2]);
            }
        }
    }
}

// ===========================================================================
// Epilogue (fp16 scratch reads)
// ===========================================================================
__global__ __launch_bounds__(256) void epilogue_kernel(
    const float* __restrict__ b1, const float* __restrict__ b2,
    float* __restrict__ out)
{
    const size_t idx = ((size_t)blockIdx.x * 256 + threadIdx.x) * 4;
    const int n = (int)(idx & (H_ - 1));
    const size_t m = idx >> 11;

    const uint2 h1 = *(const uint2*)(g_gates_h + m * TWOH + n);
    const uint2 h2 = *(const uint2*)(g_gates_h + m * TWOH + H_ + n);
    const uint2 hm = *(const uint2*)(g_merge_h + idx);
    const float4 v1 = *(const float4*)(b1 + n);
    const float4 v2 = *(const float4*)(b2 + n);

    const float2 g1a = __half22float2(*(const __half2*)&h1.x);
    const float2 g1b = __half22float2(*(const __half2*)&h1.y);
    const float2 g2a = __half22float2(*(const __half2*)&h2.x);
    const float2 g2b = __half22float2(*(const __half2*)&h2.y);
    const float2 mva = __half22float2(*(const __half2*)&hm.x);
    const float2 mvb = __half22float2(*(const __half2*)&hm.y);

    float4 r;
    { const float st = tanhf(g1a.x + v1.x);
      const float u = 1.0f / (1.0f + __expf(-(g2a.x + v2.x)));
      r.x = u * st + (1.0f - u) * mva.x; }
    { const float st = tanhf(g1a.y + v1.y);
      const float u = 1.0f / (1.0f + __expf(-(g2a.y + v2.y)));
      r.y = u * st + (1.0f - u) * mva.y; }
    { const float st = tanhf(g1b.x + v1.z);
      const float u = 1.0f / (1.0f + __expf(-(g2b.x + v2.z)));
      r.z = u * st + (1.0f - u) * mvb.x; }
    { const float st = tanhf(g1b.y + v1.w);
      const float u = 1.0f / (1.0f + __expf(-(g2b.y + v2.w)));
      r.w = u * st + (1.0f - u) * mvb.y; }

    *(float4*)(out + idx) = r;
    *(float4*)(out + idx + (size_t)B_ * H_) = r;
}

// ===========================================================================
extern "C" void kernel_launch(void* const* d_in, const int* in_sizes, int n_in,
                              void* d_out, int out_size)
{
    const float* x0 = (const float*)d_in[0];
    const float* x1 = (const float*)d_in[1];
    const float* h0 = (const float*)d_in[2];
    const float* h1 = (const float*)d_in[3];
    const float* W1 = (const float*)d_in[4];
    const float* b1 = (const float*)d_in[5];
    const float* W2 = (const float*)d_in[6];
    const float* b2 = (const float*)d_in[7];
    const float* Wm = (const float*)d_in[8];
    float* out = (float*)d_out;

    __half *wh, *wmh, *sh;
    cudaGetSymbolAddress((void**)&wh, g_Wh);
    cudaGetSymbolAddress((void**)&wmh, g_Wmh);
    cudaGetSymbolAddress((void**)&sh, g_sh);

    static bool attr_set = false;
    if (!attr_set) {
        cudaFuncSetAttribute(fused_mma, cudaFuncAttributeMaxDynamicSharedMemorySize, G_SMEM_B);
        attr_set = true;
    }

    pack_all<<<77824, 256>>>(W1, W2, Wm, h0, h1, wh, wmh, sh);

    fused_mma<<<1536, 256, G_SMEM_B>>>(wh, wmh, sh, x0, x1);

    epilogue_kernel<<<(unsigned)((size_t)B_ * H_ / 4 / 256), 256>>>(b1, b2, out);
}

// round 16
// speedup vs baseline: 1.1082x; 1.0873x over previous
#include <cuda_runtime.h>
#include <cuda_fp16.h>
#include <cstdint>

#define B_    4096
#define H_    2048
#define TWOH  4096

// ---------------- device scratch ----------------
__device__ __half g_Wh[(size_t)8 * TWOH * TWOH];   // [8][4096 j][4096 n] (W1 | W2 on n)
__device__ __half g_Wmh[(size_t)TWOH * H_];        // [4096 j][2048 n]
__device__ __half g_sh[(size_t)B_ * TWOH];         // [4096 m][4096 j]  (h0 | h1 on j)
__device__ __half g_gates_h[(size_t)B_ * TWOH];    // [B][4096] g1 | g2 (fp16)
__device__ __half g_merge_h[(size_t)B_ * H_];      // fp16

// ---------------- helpers ----------------
__device__ __forceinline__ uint32_t smem_u32(const void* p) {
    uint32_t a;
    asm("{ .reg .u64 t; cvta.to.shared.u64 t, %1; cvt.u32.u64 %0, t; }" : "=r"(a) : "l"(p));
    return a;
}
__device__ __forceinline__ void cpa16(uint32_t dst, const void* src) {
    asm volatile("cp.async.cg.shared.global [%0], [%1], 16;" :: "r"(dst), "l"(src));
}
#define CP_COMMIT() asm volatile("cp.async.commit_group;")
#define CP_WAIT2()  asm volatile("cp.async.wait_group 2;")
#define CP_WAIT0()  asm volatile("cp.async.wait_group 0;")

__device__ __forceinline__ uint32_t pk2h(float hi, float lo) {
    uint32_t d; asm("cvt.rn.f16x2.f32 %0, %1, %2;" : "=r"(d) : "f"(hi), "f"(lo)); return d;
}
__device__ __forceinline__ uint32_t hmul2(uint32_t a, uint32_t b) {
    uint32_t d; asm("mul.rn.f16x2 %0, %1, %2;" : "=r"(d) : "r"(a), "r"(b)); return d;
}
__device__ __forceinline__ void ldsm4(uint32_t& r0, uint32_t& r1, uint32_t& r2, uint32_t& r3,
                                      uint32_t addr) {
    asm volatile("ldmatrix.sync.aligned.m8n8.x4.shared.b16 {%0,%1,%2,%3}, [%4];"
                 : "=r"(r0), "=r"(r1), "=r"(r2), "=r"(r3) : "r"(addr));
}
__device__ __forceinline__ void ldsm4t(uint32_t& r0, uint32_t& r1, uint32_t& r2, uint32_t& r3,
                                       uint32_t addr) {
    asm volatile("ldmatrix.sync.aligned.m8n8.x4.trans.shared.b16 {%0,%1,%2,%3}, [%4];"
                 : "=r"(r0), "=r"(r1), "=r"(r2), "=r"(r3) : "r"(addr));
}
__device__ __forceinline__ void mma16(float* c, const uint32_t* a, const uint32_t* b) {
    asm volatile(
        "mma.sync.aligned.m16n8k16.row.col.f32.f16.f16.f32 "
        "{%0,%1,%2,%3}, {%4,%5,%6,%7}, {%8,%9}, {%0,%1,%2,%3};"
        : "+f"(c[0]), "+f"(c[1]), "+f"(c[2]), "+f"(c[3])
        : "r"(a[0]), "r"(a[1]), "r"(a[2]), "r"(a[3]), "r"(b[0]), "r"(b[1]));
}

// ---------------- pack kernels (8 halfs/thread) ----------------
__global__ __launch_bounds__(256) void pack_W(const float* __restrict__ W1,
                                              const float* __restrict__ W2,
                                              __half* __restrict__ dst) {
    const size_t idx = ((size_t)blockIdx.x * 256 + threadIdx.x) * 8;
    const int ng = (int)(idx & (TWOH - 1));
    const size_t ij = idx >> 12;
    const float* src = (ng < H_) ? (W1 + ij * H_ + ng) : (W2 + ij * H_ + (ng - H_));
    const float4 v0 = *(const float4*)src;
    const float4 v1 = *(const float4*)(src + 4);
    uint4 o;
    o.x = pk2h(v0.y, v0.x); o.y = pk2h(v0.w, v0.z);
    o.z = pk2h(v1.y, v1.x); o.w = pk2h(v1.w, v1.z);
    *(uint4*)(dst + idx) = o;
}
__global__ __launch_bounds__(256) void pack_s(const float* __restrict__ h0,
                                              const float* __restrict__ h1,
                                              __half* __restrict__ dst) {
    const size_t idx = ((size_t)blockIdx.x * 256 + threadIdx.x) * 8;
    const int j = (int)(idx & (TWOH - 1));
    const size_t m = idx >> 12;
    const float* src = (j < H_) ? (h0 + m * H_ + j) : (h1 + m * H_ + (j - H_));
    const float4 v0 = *(const float4*)src;
    const float4 v1 = *(const float4*)(src + 4);
    uint4 o;
    o.x = pk2h(v0.y, v0.x); o.y = pk2h(v0.w, v0.z);
    o.z = pk2h(v1.y, v1.x); o.w = pk2h(v1.w, v1.z);
    *(uint4*)(dst + idx) = o;
}
__global__ __launch_bounds__(256) void pack_Wm(const float* __restrict__ src,
                                               __half* __restrict__ dst) {
    const size_t idx = ((size_t)blockIdx.x * 256 + threadIdx.x) * 8;
    const float4 v0 = *(const float4*)(src + idx);
    const float4 v1 = *(const float4*)(src + idx + 4);
    uint4 o;
    o.x = pk2h(v0.y, v0.x); o.y = pk2h(v0.w, v0.z);
    o.z = pk2h(v1.y, v1.x); o.w = pk2h(v1.w, v1.z);
    *(uint4*)(dst + idx) = o;
}

// ---------------- smem layout ----------------
#define GA_ROW    40
#define GA_STG    (128 * GA_ROW)            // 5120 halfs (10240 B)
#define GB_ROW    136
#define GB_STG    (64 * GB_ROW)             // 8704 halfs (17408 B)
#define GB_OFF_B  (2 * GA_STG * 2)          // 20480 bytes
#define GXD_OFF_W ((GB_OFF_B + 4 * GB_STG * 2) / 4)
#define G_SMEM_B  (GB_OFF_B + 4 * GB_STG * 2 + 128 * 9 * 4)   // 94720
#define MB_STG    (32 * GB_ROW)             // 4352 halfs
#define MB_OFF_B  (4 * GA_STG * 2)          // 40960 bytes

// ===========================================================================
// Fused GEMM kernel. Tiles 0..1023: gates; 1024..1535: merge.
// Gates: 512 steps, K=64/step, 4-stage B ring, wait_group 2. fp16 writeback.
// ===========================================================================
__global__ __launch_bounds__(256, 2) void fused_mma(
    const __half* __restrict__ Wh, const __half* __restrict__ Wmh,
    const __half* __restrict__ sh,
    const float* __restrict__ x0, const float* __restrict__ x1)
{
    extern __shared__ __align__(16) char smc[];
    uint32_t* usm = (uint32_t*)smc;
    const uint32_t smb = smem_u32(smc);
    const int tid = threadIdx.x, lane = tid & 31, wid = tid >> 5;
    const int wm = wid & 3, wn = wid >> 2;
    const int lr = lane >> 2, lc = lane & 3;
    const int tile = blockIdx.x;

    const uint32_t a_lane_off = (uint32_t)(lane & 15) * (GA_ROW * 2) +
                                ((lane >> 4) & 1) * 16;
    const uint32_t b_lane_off = (uint32_t)(lane & 15) * (GB_ROW * 2) +
                                (uint32_t)(wn * 64 + ((lane >> 4) << 3)) * 2;

    float acc[2][8][4];
#pragma unroll
    for (int mt = 0; mt < 2; mt++)
#pragma unroll
        for (int nt = 0; nt < 8; nt++)
#pragma unroll
            for (int q = 0; q < 4; q++) acc[mt][nt][q] = 0.f;

    if (tile < 1024) {
        // ================= gates path =================
        const int m0 = (tile & 31) * 128;       // m fastest -> W dedup in L2
        const int n0 = (tile >> 5) * 128;

        for (int idx = tid; idx < 1024; idx += 256) {
            const int row = idx >> 3, i = idx & 7;
            const float v = (i < 4) ? x0[(size_t)(m0 + row) * 4 + i]
                                    : x1[(size_t)(m0 + row) * 4 + (i - 4)];
            usm[GXD_OFF_W + row * 9 + i] = pk2h(v, v);
        }

        auto issue_B = [&](int s) {
            const int jb = s >> 2, i0 = (s & 3) * 2, st = s & 3;
#pragma unroll
            for (int it = 0; it < 4; it++) {
                const int idx = it * 256 + tid, row = idx >> 4, c = idx & 15;
                const int slab = i0 + (row >> 5), jr = jb * 32 + (row & 31);
                cpa16(smb + GB_OFF_B + (uint32_t)(st * GB_STG + row * GB_ROW + c * 8) * 2,
                      Wh + ((size_t)slab * TWOH + jr) * TWOH + n0 + c * 8);
            }
        };
        auto issue_A = [&](int jb) {
#pragma unroll
            for (int it = 0; it < 2; it++) {
                const int idx = it * 256 + tid, row = idx >> 2, c = idx & 3;
                cpa16(smb + (uint32_t)(((jb & 1) * 128 + row) * GA_ROW + c * 8) * 2,
                      sh + (size_t)(m0 + row) * TWOH + jb * 32 + c * 8);
            }
        };

        issue_A(0); issue_B(0); CP_COMMIT();
        issue_B(1); CP_COMMIT();
        issue_B(2); CP_COMMIT();

        uint32_t areg[2][2][4];

        for (int s = 0; s < 512; s++) {
            const int jb = s >> 2, q = s & 3, i0 = q * 2;

            if (s >= 509) { CP_WAIT0(); } else { CP_WAIT2(); }
            __syncthreads();

            if (q == 0) {
                const uint32_t ab = smb + (uint32_t)((jb & 1) * 128 + wm * 32) * (GA_ROW * 2);
#pragma unroll
                for (int mt = 0; mt < 2; mt++)
#pragma unroll
                    for (int ks = 0; ks < 2; ks++)
                        ldsm4(areg[mt][ks][0], areg[mt][ks][1],
                              areg[mt][ks][2], areg[mt][ks][3],
                              ab + (uint32_t)mt * 16 * (GA_ROW * 2) + a_lane_off + ks * 32);
            }

            uint32_t xd[2][4];
#pragma unroll
            for (int h = 0; h < 2; h++)
#pragma unroll
                for (int mt = 0; mt < 2; mt++) {
                    xd[h][mt * 2]     = usm[GXD_OFF_W + (wm * 32 + mt * 16 + lr) * 9 + i0 + h];
                    xd[h][mt * 2 + 1] = usm[GXD_OFF_W + (wm * 32 + mt * 16 + 8 + lr) * 9 + i0 + h];
                }

            const uint32_t bb = smb + GB_OFF_B + (uint32_t)(s & 3) * (GB_STG * 2);
#pragma unroll
            for (int h = 0; h < 2; h++) {
                const uint32_t bh = bb + (uint32_t)h * 32 * (GB_ROW * 2);
#pragma unroll
                for (int ks = 0; ks < 2; ks++) {
                    uint32_t bfr[8][2];
#pragma unroll
                    for (int p = 0; p < 4; p++) {
                        uint32_t r0, r1, r2, r3;
                        ldsm4t(r0, r1, r2, r3,
                               bh + (uint32_t)ks * 16 * (GB_ROW * 2) + b_lane_off + p * 32);
                        bfr[2 * p][0] = r0; bfr[2 * p][1] = r1;
                        bfr[2 * p + 1][0] = r2; bfr[2 * p + 1][1] = r3;
                    }
#pragma unroll
                    for (int mt = 0; mt < 2; mt++) {
                        uint32_t a[4];
                        a[0] = hmul2(areg[mt][ks][0], xd[h][2 * mt]);
                        a[1] = hmul2(areg[mt][ks][1], xd[h][2 * mt + 1]);
                        a[2] = hmul2(areg[mt][ks][2], xd[h][2 * mt]);
                        a[3] = hmul2(areg[mt][ks][3], xd[h][2 * mt + 1]);
#pragma unroll
                        for (int nt = 0; nt < 8; nt++) mma16(acc[mt][nt], a, bfr[nt]);
                    }
                }
            }

            if (s + 3 < 512) {
                issue_B(s + 3);
                if (q == 0 && jb + 1 < 128) issue_A(jb + 1);
                CP_COMMIT();
            }
        }

#pragma unroll
        for (int mt = 0; mt < 2; mt++) {
            const int rg = m0 + wm * 32 + mt * 16 + lr;
#pragma unroll
            for (int nt = 0; nt < 8; nt++) {
                const int cg = n0 + wn * 64 + nt * 8 + 2 * lc;
                *(uint32_t*)(g_gates_h + (size_t)rg * TWOH + cg) =
                    pk2h(acc[mt][nt][1], acc[mt][nt][0]);
                *(uint32_t*)(g_gates_h + (size_t)(rg + 8) * TWOH + cg) =
                    pk2h(acc[mt][nt][3], acc[mt][nt][2]);
            }
        }
    } else {
        // ================= merge path =================
        const int t = tile - 1024;
        const int m0 = (t & 31) * 128;
        const int n0 = (t >> 5) * 128;

        auto issue_AB = [&](int s) {
            const int st = s & 3;
#pragma unroll
            for (int it = 0; it < 2; it++) {
                const int idx = it * 256 + tid, row = idx >> 2, c = idx & 3;
                cpa16(smb + (uint32_t)((st * 128 + row) * GA_ROW + c * 8) * 2,
                      sh + (size_t)(m0 + row) * TWOH + s * 32 + c * 8);
            }
#pragma unroll
            for (int it = 0; it < 2; it++) {
                const int idx = it * 256 + tid, row = idx >> 4, c = idx & 15;
                cpa16(smb + MB_OFF_B + (uint32_t)(st * MB_STG + row * GB_ROW + c * 8) * 2,
                      Wmh + (size_t)(s * 32 + row) * H_ + n0 + c * 8);
            }
        };

        issue_AB(0); CP_COMMIT();
        issue_AB(1); CP_COMMIT();
        issue_AB(2); CP_COMMIT();

        for (int s = 0; s < 128; s++) {
            if (s >= 125) { CP_WAIT0(); } else { CP_WAIT2(); }
            __syncthreads();

            uint32_t areg[2][2][4];
            const uint32_t ab = smb + (uint32_t)((s & 3) * 128 + wm * 32) * (GA_ROW * 2);
#pragma unroll
            for (int mt = 0; mt < 2; mt++)
#pragma unroll
                for (int ks = 0; ks < 2; ks++)
                    ldsm4(areg[mt][ks][0], areg[mt][ks][1], areg[mt][ks][2], areg[mt][ks][3],
                          ab + (uint32_t)mt * 16 * (GA_ROW * 2) + a_lane_off + ks * 32);

            const uint32_t bb = smb + MB_OFF_B + (uint32_t)((s & 3) * MB_STG) * 2;
#pragma unroll
            for (int ks = 0; ks < 2; ks++) {
                uint32_t bfr[8][2];
#pragma unroll
                for (int p = 0; p < 4; p++) {
                    uint32_t r0, r1, r2, r3;
                    ldsm4t(r0, r1, r2, r3,
                           bb + (uint32_t)ks * 16 * (GB_ROW * 2) + b_lane_off + p * 32);
                    bfr[2 * p][0] = r0; bfr[2 * p][1] = r1;
                    bfr[2 * p + 1][0] = r2; bfr[2 * p + 1][1] = r3;
                }
#pragma unroll
                for (int mt = 0; mt < 2; mt++)
#pragma unroll
                    for (int nt = 0; nt < 8; nt++)
                        mma16(acc[mt][nt], areg[mt][ks], bfr[nt]);
            }

            if (s + 3 < 128) { issue_AB(s + 3); CP_COMMIT(); }
        }

#pragma unroll
        for (int mt = 0; mt < 2; mt++) {
            const int rg = m0 + wm * 32 + mt * 16 + lr;
#pragma unroll
            for (int nt = 0; nt < 8; nt++) {
                const int cg = n0 + wn * 64 + nt * 8 + 2 * lc;
                *(uint32_t*)(g_merge_h + (size_t)rg * H_ + cg) =
                    pk2h(acc[mt][nt][1], acc[mt][nt][0]);
                *(uint32_t*)(g_merge_h + (size_t)(rg + 8) * H_ + cg) =
                    pk2h(acc[mt][nt][3], acc[mt][nt][2]);
            }
        }
    }
}

// ===========================================================================
// Epilogue (fp16 scratch reads)
// ===========================================================================
__global__ __launch_bounds__(256) void epilogue_kernel(
    const float* __restrict__ b1, const float* __restrict__ b2,
    float* __restrict__ out)
{
    const size_t idx = ((size_t)blockIdx.x * 256 + threadIdx.x) * 4;
    const int n = (int)(idx & (H_ - 1));
    const size_t m = idx >> 11;

    const uint2 h1 = *(const uint2*)(g_gates_h + m * TWOH + n);
    const uint2 h2 = *(const uint2*)(g_gates_h + m * TWOH + H_ + n);
    const uint2 hm = *(const uint2*)(g_merge_h + idx);
    const float4 v1 = *(const float4*)(b1 + n);
    const float4 v2 = *(const float4*)(b2 + n);

    const float2 g1a = __half22float2(*(const __half2*)&h1.x);
    const float2 g1b = __half22float2(*(const __half2*)&h1.y);
    const float2 g2a = __half22float2(*(const __half2*)&h2.x);
    const float2 g2b = __half22float2(*(const __half2*)&h2.y);
    const float2 mva = __half22float2(*(const __half2*)&hm.x);
    const float2 mvb = __half22float2(*(const __half2*)&hm.y);

    float4 r;
    { const float st = tanhf(g1a.x + v1.x);
      const float u = 1.0f / (1.0f + __expf(-(g2a.x + v2.x)));
      r.x = u * st + (1.0f - u) * mva.x; }
    { const float st = tanhf(g1a.y + v1.y);
      const float u = 1.0f / (1.0f + __expf(-(g2a.y + v2.y)));
      r.y = u * st + (1.0f - u) * mva.y; }
    { const float st = tanhf(g1b.x + v1.z);
      const float u = 1.0f / (1.0f + __expf(-(g2b.x + v2.z)));
      r.z = u * st + (1.0f - u) * mvb.x; }
    { const float st = tanhf(g1b.y + v1.w);
      const float u = 1.0f / (1.0f + __expf(-(g2b.y + v2.w)));
      r.w = u * st + (1.0f - u) * mvb.y; }

    *(float4*)(out + idx) = r;
    *(float4*)(out + idx + (size_t)B_ * H_) = r;
}

// ===========================================================================
extern "C" void kernel_launch(void* const* d_in, const int* in_sizes, int n_in,
                              void* d_out, int out_size)
{
    const float* x0 = (const float*)d_in[0];
    const float* x1 = (const float*)d_in[1];
    const float* h0 = (const float*)d_in[2];
    const float* h1 = (const float*)d_in[3];
    const float* W1 = (const float*)d_in[4];
    const float* b1 = (const float*)d_in[5];
    const float* W2 = (const float*)d_in[6];
    const float* b2 = (const float*)d_in[7];
    const float* Wm = (const float*)d_in[8];
    float* out = (float*)d_out;

    __half *wh, *wmh, *sh;
    cudaGetSymbolAddress((void**)&wh, g_Wh);
    cudaGetSymbolAddress((void**)&wmh, g_Wmh);
    cudaGetSymbolAddress((void**)&sh, g_sh);

    static bool attr_set = false;
    if (!attr_set) {
        cudaFuncSetAttribute(fused_mma, cudaFuncAttributeMaxDynamicSharedMemorySize, G_SMEM_B);
        attr_set = true;
    }

    pack_W <<<65536, 256>>>(W1, W2, wh);
    pack_s <<<8192, 256>>>(h0, h1, sh);
    pack_Wm<<<4096, 256>>>(Wm, wmh);

    fused_mma<<<1536, 256, G_SMEM_B>>>(wh, wmh, sh, x0, x1);

    epilogue_kernel<<<(unsigned)((size_t)B_ * H_ / 4 / 256), 256>>>(b1, b2, out);
}

// round 17
// speedup vs baseline: 1.1179x; 1.0087x over previous
#include <cuda_runtime.h>
#include <cuda_fp16.h>
#include <cstdint>

#define B_    4096
#define H_    2048
#define TWOH  4096

// ---------------- device scratch ----------------
__device__ __half g_Wh[(size_t)8 * TWOH * TWOH];   // [8][4096 j][4096 n] (W1 | W2 on n)
__device__ __half g_Wmh[(size_t)TWOH * H_];        // [4096 j][2048 n]
__device__ __half g_sh[(size_t)B_ * TWOH];         // [4096 m][4096 j]  (h0 | h1 on j)
__device__ __half g_gates_h[(size_t)B_ * TWOH];    // [B][4096] g1 | g2 (fp16, atomic-accumulated)
__device__ __half g_merge_h[(size_t)B_ * H_];      // fp16

// ---------------- helpers ----------------
__device__ __forceinline__ uint32_t smem_u32(const void* p) {
    uint32_t a;
    asm("{ .reg .u64 t; cvta.to.shared.u64 t, %1; cvt.u32.u64 %0, t; }" : "=r"(a) : "l"(p));
    return a;
}
__device__ __forceinline__ void cpa16(uint32_t dst, const void* src) {
    asm volatile("cp.async.cg.shared.global [%0], [%1], 16;" :: "r"(dst), "l"(src));
}
#define CP_COMMIT() asm volatile("cp.async.commit_group;")
#define CP_WAIT2()  asm volatile("cp.async.wait_group 2;")
#define CP_WAIT0()  asm volatile("cp.async.wait_group 0;")

__device__ __forceinline__ uint32_t pk2h(float hi, float lo) {
    uint32_t d; asm("cvt.rn.f16x2.f32 %0, %1, %2;" : "=r"(d) : "f"(hi), "f"(lo)); return d;
}
__device__ __forceinline__ uint32_t hmul2(uint32_t a, uint32_t b) {
    uint32_t d; asm("mul.rn.f16x2 %0, %1, %2;" : "=r"(d) : "r"(a), "r"(b)); return d;
}
__device__ __forceinline__ void ldsm4(uint32_t& r0, uint32_t& r1, uint32_t& r2, uint32_t& r3,
                                      uint32_t addr) {
    asm volatile("ldmatrix.sync.aligned.m8n8.x4.shared.b16 {%0,%1,%2,%3}, [%4];"
                 : "=r"(r0), "=r"(r1), "=r"(r2), "=r"(r3) : "r"(addr));
}
__device__ __forceinline__ void ldsm4t(uint32_t& r0, uint32_t& r1, uint32_t& r2, uint32_t& r3,
                                       uint32_t addr) {
    asm volatile("ldmatrix.sync.aligned.m8n8.x4.trans.shared.b16 {%0,%1,%2,%3}, [%4];"
                 : "=r"(r0), "=r"(r1), "=r"(r2), "=r"(r3) : "r"(addr));
}
__device__ __forceinline__ void mma16(float* c, const uint32_t* a, const uint32_t* b) {
    asm volatile(
        "mma.sync.aligned.m16n8k16.row.col.f32.f16.f16.f32 "
        "{%0,%1,%2,%3}, {%4,%5,%6,%7}, {%8,%9}, {%0,%1,%2,%3};"
        : "+f"(c[0]), "+f"(c[1]), "+f"(c[2]), "+f"(c[3])
        : "r"(a[0]), "r"(a[1]), "r"(a[2]), "r"(a[3]), "r"(b[0]), "r"(b[1]));
}
__device__ __forceinline__ void red_h2(__half* p, uint32_t packed) {
    __half2 v = *reinterpret_cast<__half2*>(&packed);
    atomicAdd(reinterpret_cast<__half2*>(p), v);
}

// ---------------- pack kernels (8 halfs/thread) ----------------
__global__ __launch_bounds__(256) void pack_W(const float* __restrict__ W1,
                                              const float* __restrict__ W2,
                                              __half* __restrict__ dst) {
    const size_t idx = ((size_t)blockIdx.x * 256 + threadIdx.x) * 8;
    const int ng = (int)(idx & (TWOH - 1));
    const size_t ij = idx >> 12;
    const float* src = (ng < H_) ? (W1 + ij * H_ + ng) : (W2 + ij * H_ + (ng - H_));
    const float4 v0 = *(const float4*)src;
    const float4 v1 = *(const float4*)(src + 4);
    uint4 o;
    o.x = pk2h(v0.y, v0.x); o.y = pk2h(v0.w, v0.z);
    o.z = pk2h(v1.y, v1.x); o.w = pk2h(v1.w, v1.z);
    *(uint4*)(dst + idx) = o;
}
__global__ __launch_bounds__(256) void pack_s(const float* __restrict__ h0,
                                              const float* __restrict__ h1,
                                              __half* __restrict__ dst) {
    const size_t idx = ((size_t)blockIdx.x * 256 + threadIdx.x) * 8;
    const int j = (int)(idx & (TWOH - 1));
    const size_t m = idx >> 12;
    const float* src = (j < H_) ? (h0 + m * H_ + j) : (h1 + m * H_ + (j - H_));
    const float4 v0 = *(const float4*)src;
    const float4 v1 = *(const float4*)(src + 4);
    uint4 o;
    o.x = pk2h(v0.y, v0.x); o.y = pk2h(v0.w, v0.z);
    o.z = pk2h(v1.y, v1.x); o.w = pk2h(v1.w, v1.z);
    *(uint4*)(dst + idx) = o;
}
__global__ __launch_bounds__(256) void pack_Wm(const float* __restrict__ src,
                                               __half* __restrict__ dst) {
    const size_t idx = ((size_t)blockIdx.x * 256 + threadIdx.x) * 8;
    const float4 v0 = *(const float4*)(src + idx);
    const float4 v1 = *(const float4*)(src + idx + 4);
    uint4 o;
    o.x = pk2h(v0.y, v0.x); o.y = pk2h(v0.w, v0.z);
    o.z = pk2h(v1.y, v1.x); o.w = pk2h(v1.w, v1.z);
    *(uint4*)(dst + idx) = o;
}

// ---------------- smem layout ----------------
#define GA_ROW    40
#define GA_STG    (128 * GA_ROW)            // 5120 halfs (10240 B)
#define GB_ROW    136
#define GB_STG    (64 * GB_ROW)             // 8704 halfs (17408 B)
#define GB_OFF_B  (2 * GA_STG * 2)          // 20480 bytes
#define GXD_OFF_W ((GB_OFF_B + 4 * GB_STG * 2) / 4)
#define G_SMEM_B  (GB_OFF_B + 4 * GB_STG * 2 + 128 * 9 * 4)   // 94720
#define MB_STG    (32 * GB_ROW)             // 4352 halfs
#define MB_OFF_B  (4 * GA_STG * 2)          // 40960 bytes

// ===========================================================================
// Fused GEMM. Tiles 0..2047: gates half-K tiles (half = tile>>10, tt = tile&1023);
// tiles 2048..2559: merge. Gates halves atomically accumulate fp16 partials.
// Gates half: 256 steps, K=64/step, 4-stage B ring, wait_group 2.
// ===========================================================================
__global__ __launch_bounds__(256, 2) void fused_mma(
    const __half* __restrict__ Wh, const __half* __restrict__ Wmh,
    const __half* __restrict__ sh,
    const float* __restrict__ x0, const float* __restrict__ x1)
{
    extern __shared__ __align__(16) char smc[];
    uint32_t* usm = (uint32_t*)smc;
    const uint32_t smb = smem_u32(smc);
    const int tid = threadIdx.x, lane = tid & 31, wid = tid >> 5;
    const int wm = wid & 3, wn = wid >> 2;
    const int lr = lane >> 2, lc = lane & 3;
    const int tile = blockIdx.x;

    const uint32_t a_lane_off = (uint32_t)(lane & 15) * (GA_ROW * 2) +
                                ((lane >> 4) & 1) * 16;
    const uint32_t b_lane_off = (uint32_t)(lane & 15) * (GB_ROW * 2) +
                                (uint32_t)(wn * 64 + ((lane >> 4) << 3)) * 2;

    float acc[2][8][4];
#pragma unroll
    for (int mt = 0; mt < 2; mt++)
#pragma unroll
        for (int nt = 0; nt < 8; nt++)
#pragma unroll
            for (int q = 0; q < 4; q++) acc[mt][nt][q] = 0.f;

    if (tile < 2048) {
        // ================= gates path (half-K tile) =================
        const int tt = tile & 1023;          // half-major order: wave keeps W dedup
        const int jb0 = (tile >> 10) * 64;   // 0 or 64
        const int m0 = (tt & 31) * 128;      // m fastest -> W dedup in L2
        const int n0 = (tt >> 5) * 128;

        for (int idx = tid; idx < 1024; idx += 256) {
            const int row = idx >> 3, i = idx & 7;
            const float v = (i < 4) ? x0[(size_t)(m0 + row) * 4 + i]
                                    : x1[(size_t)(m0 + row) * 4 + (i - 4)];
            usm[GXD_OFF_W + row * 9 + i] = pk2h(v, v);
        }

        auto issue_B = [&](int s) {
            const int jb = jb0 + (s >> 2), i0 = (s & 3) * 2, st = s & 3;
#pragma unroll
            for (int it = 0; it < 4; it++) {
                const int idx = it * 256 + tid, row = idx >> 4, c = idx & 15;
                const int slab = i0 + (row >> 5), jr = jb * 32 + (row & 31);
                cpa16(smb + GB_OFF_B + (uint32_t)(st * GB_STG + row * GB_ROW + c * 8) * 2,
                      Wh + ((size_t)slab * TWOH + jr) * TWOH + n0 + c * 8);
            }
        };
        auto issue_A = [&](int jb) {
#pragma unroll
            for (int it = 0; it < 2; it++) {
                const int idx = it * 256 + tid, row = idx >> 2, c = idx & 3;
                cpa16(smb + (uint32_t)(((jb & 1) * 128 + row) * GA_ROW + c * 8) * 2,
                      sh + (size_t)(m0 + row) * TWOH + jb * 32 + c * 8);
            }
        };

        issue_A(jb0); issue_B(0); CP_COMMIT();
        issue_B(1); CP_COMMIT();
        issue_B(2); CP_COMMIT();

        uint32_t areg[2][2][4];

        for (int s = 0; s < 256; s++) {
            const int jb = jb0 + (s >> 2), q = s & 3, i0 = q * 2;

            if (s >= 253) { CP_WAIT0(); } else { CP_WAIT2(); }
            __syncthreads();

            if (q == 0) {
                const uint32_t ab = smb + (uint32_t)((jb & 1) * 128 + wm * 32) * (GA_ROW * 2);
#pragma unroll
                for (int mt = 0; mt < 2; mt++)
#pragma unroll
                    for (int ks = 0; ks < 2; ks++)
                        ldsm4(areg[mt][ks][0], areg[mt][ks][1],
                              areg[mt][ks][2], areg[mt][ks][3],
                              ab + (uint32_t)mt * 16 * (GA_ROW * 2) + a_lane_off + ks * 32);
            }

            uint32_t xd[2][4];
#pragma unroll
            for (int h = 0; h < 2; h++)
#pragma unroll
                for (int mt = 0; mt < 2; mt++) {
                    xd[h][mt * 2]     = usm[GXD_OFF_W + (wm * 32 + mt * 16 + lr) * 9 + i0 + h];
                    xd[h][mt * 2 + 1] = usm[GXD_OFF_W + (wm * 32 + mt * 16 + 8 + lr) * 9 + i0 + h];
                }

            const uint32_t bb = smb + GB_OFF_B + (uint32_t)(s & 3) * (GB_STG * 2);
#pragma unroll
            for (int h = 0; h < 2; h++) {
                const uint32_t bh = bb + (uint32_t)h * 32 * (GB_ROW * 2);
#pragma unroll
                for (int ks = 0; ks < 2; ks++) {
                    uint32_t bfr[8][2];
#pragma unroll
                    for (int p = 0; p < 4; p++) {
                        uint32_t r0, r1, r2, r3;
                        ldsm4t(r0, r1, r2, r3,
                               bh + (uint32_t)ks * 16 * (GB_ROW * 2) + b_lane_off + p * 32);
                        bfr[2 * p][0] = r0; bfr[2 * p][1] = r1;
                        bfr[2 * p + 1][0] = r2; bfr[2 * p + 1][1] = r3;
                    }
#pragma unroll
                    for (int mt = 0; mt < 2; mt++) {
                        uint32_t a[4];
                        a[0] = hmul2(areg[mt][ks][0], xd[h][2 * mt]);
                        a[1] = hmul2(areg[mt][ks][1], xd[h][2 * mt + 1]);
                        a[2] = hmul2(areg[mt][ks][2], xd[h][2 * mt]);
                        a[3] = hmul2(areg[mt][ks][3], xd[h][2 * mt + 1]);
#pragma unroll
                        for (int nt = 0; nt < 8; nt++) mma16(acc[mt][nt], a, bfr[nt]);
                    }
                }
            }

            if (s + 3 < 256) {
                issue_B(s + 3);
                if (q == 0 && jb + 1 < jb0 + 64) issue_A(jb + 1);
                CP_COMMIT();
            }
        }

        // atomic fp16 accumulation into zero-initialized scratch
#pragma unroll
        for (int mt = 0; mt < 2; mt++) {
            const int rg = m0 + wm * 32 + mt * 16 + lr;
#pragma unroll
            for (int nt = 0; nt < 8; nt++) {
                const int cg = n0 + wn * 64 + nt * 8 + 2 * lc;
                red_h2(g_gates_h + (size_t)rg * TWOH + cg,
                       pk2h(acc[mt][nt][1], acc[mt][nt][0]));
                red_h2(g_gates_h + (size_t)(rg + 8) * TWOH + cg,
                       pk2h(acc[mt][nt][3], acc[mt][nt][2]));
            }
        }
    } else {
        // ================= merge path =================
        const int t = tile - 2048;
        const int m0 = (t & 31) * 128;
        const int n0 = (t >> 5) * 128;

        auto issue_AB = [&](int s) {
            const int st = s & 3;
#pragma unroll
            for (int it = 0; it < 2; it++) {
                const int idx = it * 256 + tid, row = idx >> 2, c = idx & 3;
                cpa16(smb + (uint32_t)((st * 128 + row) * GA_ROW + c * 8) * 2,
                      sh + (size_t)(m0 + row) * TWOH + s * 32 + c * 8);
            }
#pragma unroll
            for (int it = 0; it < 2; it++) {
                const int idx = it * 256 + tid, row = idx >> 4, c = idx & 15;
                cpa16(smb + MB_OFF_B + (uint32_t)(st * MB_STG + row * GB_ROW + c * 8) * 2,
                      Wmh + (size_t)(s * 32 + row) * H_ + n0 + c * 8);
            }
        };

        issue_AB(0); CP_COMMIT();
        issue_AB(1); CP_COMMIT();
        issue_AB(2); CP_COMMIT();

        for (int s = 0; s < 128; s++) {
            if (s >= 125) { CP_WAIT0(); } else { CP_WAIT2(); }
            __syncthreads();

            uint32_t areg[2][2][4];
            const uint32_t ab = smb + (uint32_t)((s & 3) * 128 + wm * 32) * (GA_ROW * 2);
#pragma unroll
            for (int mt = 0; mt < 2; mt++)
#pragma unroll
                for (int ks = 0; ks < 2; ks++)
                    ldsm4(areg[mt][ks][0], areg[mt][ks][1], areg[mt][ks][2], areg[mt][ks][3],
                          ab + (uint32_t)mt * 16 * (GA_ROW * 2) + a_lane_off + ks * 32);

            const uint32_t bb = smb + MB_OFF_B + (uint32_t)((s & 3) * MB_STG) * 2;
#pragma unroll
            for (int ks = 0; ks < 2; ks++) {
                uint32_t bfr[8][2];
#pragma unroll
                for (int p = 0; p < 4; p++) {
                    uint32_t r0, r1, r2, r3;
                    ldsm4t(r0, r1, r2, r3,
                           bb + (uint32_t)ks * 16 * (GB_ROW * 2) + b_lane_off + p * 32);
                    bfr[2 * p][0] = r0; bfr[2 * p][1] = r1;
                    bfr[2 * p + 1][0] = r2; bfr[2 * p + 1][1] = r3;
                }
#pragma unroll
                for (int mt = 0; mt < 2; mt++)
#pragma unroll
                    for (int nt = 0; nt < 8; nt++)
                        mma16(acc[mt][nt], areg[mt][ks], bfr[nt]);
            }

            if (s + 3 < 128) { issue_AB(s + 3); CP_COMMIT(); }
        }

#pragma unroll
        for (int mt = 0; mt < 2; mt++) {
            const int rg = m0 + wm * 32 + mt * 16 + lr;
#pragma unroll
            for (int nt = 0; nt < 8; nt++) {
                const int cg = n0 + wn * 64 + nt * 8 + 2 * lc;
                *(uint32_t*)(g_merge_h + (size_t)rg * H_ + cg) =
                    pk2h(acc[mt][nt][1], acc[mt][nt][0]);
                *(uint32_t*)(g_merge_h + (size_t)(rg + 8) * H_ + cg) =
                    pk2h(acc[mt][nt][3], acc[mt][nt][2]);
            }
        }
    }
}

// ===========================================================================
// Epilogue (fp16 scratch reads)
// ===========================================================================
__global__ __launch_bounds__(256) void epilogue_kernel(
    const float* __restrict__ b1, const float* __restrict__ b2,
    float* __restrict__ out)
{
    const size_t idx = ((size_t)blockIdx.x * 256 + threadIdx.x) * 4;
    const int n = (int)(idx & (H_ - 1));
    const size_t m = idx >> 11;

    const uint2 h1 = *(const uint2*)(g_gates_h + m * TWOH + n);
    const uint2 h2 = *(const uint2*)(g_gates_h + m * TWOH + H_ + n);
    const uint2 hm = *(const uint2*)(g_merge_h + idx);
    const float4 v1 = *(const float4*)(b1 + n);
    const float4 v2 = *(const float4*)(b2 + n);

    const float2 g1a = __half22float2(*(const __half2*)&h1.x);
    const float2 g1b = __half22float2(*(const __half2*)&h1.y);
    const float2 g2a = __half22float2(*(const __half2*)&h2.x);
    const float2 g2b = __half22float2(*(const __half2*)&h2.y);
    const float2 mva = __half22float2(*(const __half2*)&hm.x);
    const float2 mvb = __half22float2(*(const __half2*)&hm.y);

    float4 r;
    { const float st = tanhf(g1a.x + v1.x);
      const float u = 1.0f / (1.0f + __expf(-(g2a.x + v2.x)));
      r.x = u * st + (1.0f - u) * mva.x; }
    { const float st = tanhf(g1a.y + v1.y);
      const float u = 1.0f / (1.0f + __expf(-(g2a.y + v2.y)));
      r.y = u * st + (1.0f - u) * mva.y; }
    { const float st = tanhf(g1b.x + v1.z);
      const float u = 1.0f / (1.0f + __expf(-(g2b.x + v2.z)));
      r.z = u * st + (1.0f - u) * mvb.x; }
    { const float st = tanhf(g1b.y + v1.w);
      const float u = 1.0f / (1.0f + __expf(-(g2b.y + v2.w)));
      r.w = u * st + (1.0f - u) * mvb.y; }

    *(float4*)(out + idx) = r;
    *(float4*)(out + idx + (size_t)B_ * H_) = r;
}

// ===========================================================================
extern "C" void kernel_launch(void* const* d_in, const int* in_sizes, int n_in,
                              void* d_out, int out_size)
{
    const float* x0 = (const float*)d_in[0];
    const float* x1 = (const float*)d_in[1];
    const float* h0 = (const float*)d_in[2];
    const float* h1 = (const float*)d_in[3];
    const float* W1 = (const float*)d_in[4];
    const float* b1 = (const float*)d_in[5];
    const float* W2 = (const float*)d_in[6];
    const float* b2 = (const float*)d_in[7];
    const float* Wm = (const float*)d_in[8];
    float* out = (float*)d_out;

    __half *wh, *wmh, *sh, *gh;
    cudaGetSymbolAddress((void**)&wh, g_Wh);
    cudaGetSymbolAddress((void**)&wmh, g_Wmh);
    cudaGetSymbolAddress((void**)&sh, g_sh);
    cudaGetSymbolAddress((void**)&gh, g_gates_h);

    static bool attr_set = false;
    if (!attr_set) {
        cudaFuncSetAttribute(fused_mma, cudaFuncAttributeMaxDynamicSharedMemorySize, G_SMEM_B);
        attr_set = true;
    }

    // zero the gates accumulator (atomic targets), capturable async memset
    cudaMemsetAsync(gh, 0, (size_t)B_ * TWOH * sizeof(__half));

    pack_W <<<65536, 256>>>(W1, W2, wh);
    pack_s <<<8192, 256>>>(h0, h1, sh);
    pack_Wm<<<4096, 256>>>(Wm, wmh);

    fused_mma<<<2560, 256, G_SMEM_B>>>(wh, wmh, sh, x0, x1);

    epilogue_kernel<<<(unsigned)((size_t)B_ * H_ / 4 / 256), 256>>>(b1, b2, out);
}